// round 2
// baseline (speedup 1.0000x reference)
#include <cuda_runtime.h>
#include <math.h>

// ---------------------------------------------------------------------------
// Self-attention: B=4, S=2048, D=1024
//   q = a@w_q + b_q ; k = a@w_k + b_k ; v = a@w_v + b_v
//   s = q @ k^T  (per batch)          [4,2048,2048]
//   p = softmax(s, axis=-1)           (in place)
//   out = p @ v                       [4,2048,1024]
// Round 1: fp32 register-tiled SGEMMs + row softmax (resubmit after infra
// failure; establishes baseline + first ncu capture).
// ---------------------------------------------------------------------------

#define BATCH 4
#define SEQ   2048
#define DIM   1024

#define BM 128
#define BN 128
#define BK 16
#define TM 8
#define TN 8
#define NTHREADS 256

// Static scratch (allocation-free rule: __device__ globals).
__device__ float g_q[BATCH * SEQ * DIM];
__device__ float g_k[BATCH * SEQ * DIM];
__device__ float g_v[BATCH * SEQ * DIM];
__device__ float g_s[BATCH * SEQ * SEQ];   // 64 MB scores / probs

// ---------------------------------------------------------------------------
// SGEMM: C = A @ B (+ bias), or C = A @ B^T when TRANS_B.
//   A: [M,K] row-major
//   B: [K,N] row-major (NN)  or  [N,K] row-major (NT)
//   batched via blockIdx.z with element strides.
// 128x128 tile, BK=16, 256 threads, 8x8 micro-tile per thread.
// ---------------------------------------------------------------------------
template<bool TRANS_B, bool HAS_BIAS>
__global__ void __launch_bounds__(NTHREADS)
sgemm_kernel(const float* __restrict__ A, const float* __restrict__ B,
             const float* __restrict__ bias, float* __restrict__ C,
             int M, int N, int K,
             long strideA, long strideB, long strideC)
{
    A += (long)blockIdx.z * strideA;
    B += (long)blockIdx.z * strideB;
    C += (long)blockIdx.z * strideC;

    __shared__ float As[BK][BM + 4];
    __shared__ float Bs[BK][BN + 4];

    const int tid = threadIdx.x;
    const int tx = tid & 15;          // 0..15  -> N direction
    const int ty = tid >> 4;          // 0..15  -> M direction
    const int m0 = blockIdx.y * BM;
    const int n0 = blockIdx.x * BN;

    float acc[TM][TN];
#pragma unroll
    for (int i = 0; i < TM; i++)
#pragma unroll
        for (int j = 0; j < TN; j++) acc[i][j] = 0.f;

    for (int k0 = 0; k0 < K; k0 += BK) {
        // ---- load A tile: 128 (m) x 16 (k), 512 float4s, 2 per thread ----
#pragma unroll
        for (int l = 0; l < 2; l++) {
            int f   = tid + l * NTHREADS;
            int row = f >> 2;            // m within tile
            int kq  = (f & 3) << 2;      // k within tile (multiple of 4)
            float4 val = *(const float4*)(A + (long)(m0 + row) * K + k0 + kq);
            As[kq + 0][row] = val.x;
            As[kq + 1][row] = val.y;
            As[kq + 2][row] = val.z;
            As[kq + 3][row] = val.w;
        }
        // ---- load B tile ----
        if (!TRANS_B) {
            // B[K,N]: 16 (k) x 128 (n), coalesced along n
#pragma unroll
            for (int l = 0; l < 2; l++) {
                int f  = tid + l * NTHREADS;
                int k  = f >> 5;             // k within tile
                int nq = (f & 31) << 2;      // n within tile
                float4 val = *(const float4*)(B + (long)(k0 + k) * N + n0 + nq);
                *(float4*)&Bs[k][nq] = val;  // row stride 132 floats (16B aligned)
            }
        } else {
            // B[N,K]: 128 (n) rows x 16 (k) cols, transpose into Bs[k][n]
#pragma unroll
            for (int l = 0; l < 2; l++) {
                int f   = tid + l * NTHREADS;
                int row = f >> 2;            // n within tile
                int kq  = (f & 3) << 2;
                float4 val = *(const float4*)(B + (long)(n0 + row) * K + k0 + kq);
                Bs[kq + 0][row] = val.x;
                Bs[kq + 1][row] = val.y;
                Bs[kq + 2][row] = val.z;
                Bs[kq + 3][row] = val.w;
            }
        }
        __syncthreads();

        // ---- compute ----
#pragma unroll
        for (int k = 0; k < BK; k++) {
            float ra[TM], rb[TN];
#pragma unroll
            for (int i = 0; i < TM; i++) ra[i] = As[k][ty * TM + i];
#pragma unroll
            for (int j = 0; j < TN; j++) rb[j] = Bs[k][tx * TN + j];
#pragma unroll
            for (int i = 0; i < TM; i++)
#pragma unroll
                for (int j = 0; j < TN; j++)
                    acc[i][j] += ra[i] * rb[j];
        }
        __syncthreads();
    }

    // ---- epilogue ----
#pragma unroll
    for (int i = 0; i < TM; i++) {
        int m = m0 + ty * TM + i;
#pragma unroll
        for (int j = 0; j < TN; j += 4) {
            int n = n0 + tx * TN + j;
            float4 val = make_float4(acc[i][j], acc[i][j+1], acc[i][j+2], acc[i][j+3]);
            if (HAS_BIAS) {
                val.x += bias[n + 0];
                val.y += bias[n + 1];
                val.z += bias[n + 2];
                val.w += bias[n + 3];
            }
            *(float4*)(C + (long)m * N + n) = val;
        }
    }
}

// ---------------------------------------------------------------------------
// Row softmax (in place). One block per row of length SEQ.
// ---------------------------------------------------------------------------
__global__ void __launch_bounds__(256)
softmax_kernel(float* __restrict__ S)
{
    float* row = S + (long)blockIdx.x * SEQ;
    __shared__ float red[256];
    const int tid = threadIdx.x;

    // 1) row max
    float m = -INFINITY;
    for (int i = tid; i < SEQ; i += 256) m = fmaxf(m, row[i]);
    red[tid] = m;
    __syncthreads();
    for (int s = 128; s > 0; s >>= 1) {
        if (tid < s) red[tid] = fmaxf(red[tid], red[tid + s]);
        __syncthreads();
    }
    m = red[0];
    __syncthreads();

    // 2) exp & sum
    float sum = 0.f;
    for (int i = tid; i < SEQ; i += 256) {
        float e = __expf(row[i] - m);
        row[i] = e;
        sum += e;
    }
    red[tid] = sum;
    __syncthreads();
    for (int s = 128; s > 0; s >>= 1) {
        if (tid < s) red[tid] += red[tid + s];
        __syncthreads();
    }
    float inv = 1.f / red[0];
    __syncthreads();

    // 3) normalize
    for (int i = tid; i < SEQ; i += 256) row[i] *= inv;
}

// ---------------------------------------------------------------------------
extern "C" void kernel_launch(void* const* d_in, const int* in_sizes, int n_in,
                              void* d_out, int out_size)
{
    const float* a   = (const float*)d_in[0];
    const float* w_q = (const float*)d_in[1];
    const float* b_q = (const float*)d_in[2];
    const float* w_k = (const float*)d_in[3];
    const float* b_k = (const float*)d_in[4];
    const float* w_v = (const float*)d_in[5];
    const float* b_v = (const float*)d_in[6];
    float* out = (float*)d_out;

    float *q, *k, *v, *s;
    cudaGetSymbolAddress((void**)&q, g_q);
    cudaGetSymbolAddress((void**)&k, g_k);
    cudaGetSymbolAddress((void**)&v, g_v);
    cudaGetSymbolAddress((void**)&s, g_s);

    const int M1 = BATCH * SEQ;   // 8192

    // 1) QKV projections: [8192,1024] @ [1024,1024] + bias
    {
        dim3 grid(DIM / BN, M1 / BM, 1);
        sgemm_kernel<false, true><<<grid, NTHREADS>>>(a, w_q, b_q, q, M1, DIM, DIM, 0, 0, 0);
        sgemm_kernel<false, true><<<grid, NTHREADS>>>(a, w_k, b_k, k, M1, DIM, DIM, 0, 0, 0);
        sgemm_kernel<false, true><<<grid, NTHREADS>>>(a, w_v, b_v, v, M1, DIM, DIM, 0, 0, 0);
    }

    // 2) scores = q @ k^T per batch: [2048,1024] @ [2048,1024]^T -> [2048,2048]
    {
        dim3 grid(SEQ / BN, SEQ / BM, BATCH);
        sgemm_kernel<true, false><<<grid, NTHREADS>>>(
            q, k, nullptr, s, SEQ, SEQ, DIM,
            (long)SEQ * DIM, (long)SEQ * DIM, (long)SEQ * SEQ);
    }

    // 3) softmax rows (in place)
    softmax_kernel<<<BATCH * SEQ, 256>>>(s);

    // 4) out = p @ v per batch: [2048,2048] @ [2048,1024] -> [2048,1024]
    {
        dim3 grid(DIM / BN, SEQ / BM, BATCH);
        sgemm_kernel<false, false><<<grid, NTHREADS>>>(
            s, v, nullptr, out, SEQ, DIM, SEQ,
            (long)SEQ * SEQ, (long)SEQ * DIM, (long)SEQ * DIM);
    }
}

// round 6
// speedup vs baseline: 2.1312x; 2.1312x over previous
#include <cuda_runtime.h>
#include <cuda_bf16.h>
#include <cstdint>
#include <math.h>

// ---------------------------------------------------------------------------
// Self-attention B=4, S=2048, D=1024 — Round 5.
// Harness compiles for base sm_100 (no 'a'): tcgen05 unavailable. Use
// mma.sync.m16n8k16 bf16 with 3-term hi/lo split (x=hi+lo; hi*hi+hi*lo+lo*hi,
// fp32 accum) => ~21-bit effective mantissa, ~1e-4 output error.
//
//   WT = W^T ; VT = V^T  (transpose kernels)
//   q/k/v = a @ WT^T + b   (NT GEMM, A[m][k], B[n][k])
//   s = q @ k^T            (NT GEMM)
//   p = softmax(s)
//   out = p @ VT^T         (NT GEMM)
// ---------------------------------------------------------------------------

#define BATCH 4
#define SEQ   2048
#define DIM   1024

// ---------------- scratch ---------------------------------------------------
__device__ float g_q [BATCH * SEQ * DIM];
__device__ float g_k [BATCH * SEQ * DIM];
__device__ float g_v [BATCH * SEQ * DIM];
__device__ float g_s [BATCH * SEQ * SEQ];     // 64 MB scores/probs
__device__ float g_wt[3 * DIM * DIM];
__device__ float g_vt[BATCH * DIM * SEQ];

// ---------------- GEMM config ----------------------------------------------
#define BM 128
#define BN 128
#define BK 32                  // fp32 k per stage (2 x k16 mma steps)
#define GTHREADS 256           // 8 warps: 2 (M) x 4 (N), warp tile 64x32

// smem: per stage 4 tiles (A_hi, A_lo, B_hi, B_lo), each 128 rows x 80B
// (64B data for 32 bf16 + 16B pad -> 8 consecutive rows cover all 32 banks)
#define ROWB   80
#define TILEB  (128 * ROWB)          // 10240
#define ST_AHI 0
#define ST_ALO (TILEB)
#define ST_BHI (2 * TILEB)
#define ST_BLO (3 * TILEB)
#define STAGEB (4 * TILEB)           // 40960
#define SMEM_SZ (2 * STAGEB)         // 81920

// ---------------- mma / ldmatrix helpers ------------------------------------
__device__ __forceinline__ uint32_t smem_u32(const void* p) {
    uint32_t a;
    asm("{ .reg .u64 t; cvta.to.shared.u64 t, %1; cvt.u32.u64 %0, t; }"
        : "=r"(a) : "l"(p));
    return a;
}
__device__ __forceinline__ void ldm_x4(uint32_t* r, uint32_t addr) {
    asm volatile("ldmatrix.sync.aligned.m8n8.x4.shared.b16 {%0,%1,%2,%3}, [%4];"
                 : "=r"(r[0]), "=r"(r[1]), "=r"(r[2]), "=r"(r[3]) : "r"(addr));
}
__device__ __forceinline__ void mma_bf16(float* c, const uint32_t* a,
                                         const uint32_t* b) {
    asm volatile(
        "mma.sync.aligned.m16n8k16.row.col.f32.bf16.bf16.f32 "
        "{%0,%1,%2,%3}, {%4,%5,%6,%7}, {%8,%9}, {%0,%1,%2,%3};"
        : "+f"(c[0]), "+f"(c[1]), "+f"(c[2]), "+f"(c[3])
        : "r"(a[0]), "r"(a[1]), "r"(a[2]), "r"(a[3]), "r"(b[0]), "r"(b[1]));
}
__device__ __forceinline__ uint32_t bpack(__nv_bfloat16 a, __nv_bfloat16 b) {
    union { __nv_bfloat162 v; uint32_t u; } t;
    t.v = __halves2bfloat162(a, b);
    return t.u;
}

// Convert 16 fp32 -> hi/lo bf16 tiles, store 2x16B each.
__device__ __forceinline__ void cvt_store16(char* hi_p, char* lo_p,
                                            const float* e) {
    uint32_t hw[8], lw[8];
#pragma unroll
    for (int j = 0; j < 8; j++) {
        float x0 = e[2 * j], x1 = e[2 * j + 1];
        __nv_bfloat16 h0 = __float2bfloat16(x0);
        __nv_bfloat16 h1 = __float2bfloat16(x1);
        float r0 = x0 - __bfloat162float(h0);
        float r1 = x1 - __bfloat162float(h1);
        hw[j] = bpack(h0, h1);
        lw[j] = bpack(__float2bfloat16(r0), __float2bfloat16(r1));
    }
    ((uint4*)hi_p)[0] = make_uint4(hw[0], hw[1], hw[2], hw[3]);
    ((uint4*)hi_p)[1] = make_uint4(hw[4], hw[5], hw[6], hw[7]);
    ((uint4*)lo_p)[0] = make_uint4(lw[0], lw[1], lw[2], lw[3]);
    ((uint4*)lo_p)[1] = make_uint4(lw[4], lw[5], lw[6], lw[7]);
}

// ---------------- bf16x3 GEMM (NT): C = A @ B^T (+bias) ---------------------
// A [M][K], B [N][K] row-major fp32; batched via blockIdx.z.
template<bool HAS_BIAS>
__global__ void __launch_bounds__(GTHREADS, 1)
bf16x3_gemm_nt(const float* __restrict__ A, const float* __restrict__ B,
               const float* __restrict__ bias, float* __restrict__ C,
               int M, int N, int K, long sA, long sB, long sC)
{
    extern __shared__ char smem[];
    const uint32_t sbase = smem_u32(smem);
    const int tid  = threadIdx.x;
    const int lane = tid & 31;
    const int wid  = tid >> 5;
    const int wm0  = (wid >> 2) * 64;   // warp M offset (0/64)
    const int wn0  = (wid & 3) * 32;    // warp N offset (0/32/64/96)
    const int m0 = blockIdx.y * BM;
    const int n0 = blockIdx.x * BN;

    const float* Ab = A + (long)blockIdx.z * sA + (long)m0 * K;
    const float* Bb = B + (long)blockIdx.z * sB + (long)n0 * K;
    float*       Cb = C + (long)blockIdx.z * sC;

    // gmem staging: thread covers row=tid>>1, k-half=(tid&1)*16
    const int grow  = tid >> 1;
    const int ghalf = tid & 1;
    const float* apt = Ab + (long)grow * K + ghalf * 16;
    const float* bpt = Bb + (long)grow * K + ghalf * 16;

    // ldmatrix per-lane address parts (bytes, tile-relative)
    const uint32_t partA = (uint32_t)((wm0 + (lane & 15)) * ROWB
                                      + ((lane >> 4) << 4));
    const uint32_t partB = (uint32_t)((wn0 + (lane & 7) + ((lane >> 4) << 3)) * ROWB
                                      + ((lane & 8) ? 16 : 0));

    float acc[4][4][4];
#pragma unroll
    for (int i = 0; i < 4; i++)
#pragma unroll
        for (int j = 0; j < 4; j++)
#pragma unroll
            for (int r = 0; r < 4; r++) acc[i][j][r] = 0.f;

    float4 aR[4], bR[4];
    const int NC = K / BK;

    // prologue: stage 0
#pragma unroll
    for (int j = 0; j < 4; j++) {
        aR[j] = ((const float4*)apt)[j];
        bR[j] = ((const float4*)bpt)[j];
    }
    {
        char* st = smem;  // stage 0
        cvt_store16(st + ST_AHI + grow * ROWB + ghalf * 32,
                    st + ST_ALO + grow * ROWB + ghalf * 32, (const float*)aR);
        cvt_store16(st + ST_BHI + grow * ROWB + ghalf * 32,
                    st + ST_BLO + grow * ROWB + ghalf * 32, (const float*)bR);
    }
    __syncthreads();

    for (int i = 0; i < NC; i++) {
        // prefetch next k-chunk into regs
        if (i + 1 < NC) {
            const float* ap = apt + (i + 1) * BK;
            const float* bp = bpt + (i + 1) * BK;
#pragma unroll
            for (int j = 0; j < 4; j++) {
                aR[j] = ((const float4*)ap)[j];
                bR[j] = ((const float4*)bp)[j];
            }
        }

        // compute on stage i&1
        {
            const uint32_t st = sbase + (uint32_t)((i & 1) * STAGEB);
#pragma unroll
            for (int ks = 0; ks < 2; ks++) {
                uint32_t ah[4][4], al[4][4], bh[4][2], bl[4][2];
#pragma unroll
                for (int mf = 0; mf < 4; mf++) {
                    uint32_t off = (uint32_t)(mf * 16 * ROWB + ks * 32) + partA;
                    ldm_x4(ah[mf], st + ST_AHI + off);
                    ldm_x4(al[mf], st + ST_ALO + off);
                }
#pragma unroll
                for (int nf2 = 0; nf2 < 2; nf2++) {
                    uint32_t off = (uint32_t)(nf2 * 16 * ROWB + ks * 32) + partB;
                    uint32_t t[4];
                    ldm_x4(t, st + ST_BHI + off);
                    bh[nf2 * 2][0] = t[0]; bh[nf2 * 2][1] = t[1];
                    bh[nf2 * 2 + 1][0] = t[2]; bh[nf2 * 2 + 1][1] = t[3];
                    ldm_x4(t, st + ST_BLO + off);
                    bl[nf2 * 2][0] = t[0]; bl[nf2 * 2][1] = t[1];
                    bl[nf2 * 2 + 1][0] = t[2]; bl[nf2 * 2 + 1][1] = t[3];
                }
#pragma unroll
                for (int nf = 0; nf < 4; nf++)
#pragma unroll
                    for (int mf = 0; mf < 4; mf++) {
                        mma_bf16(acc[mf][nf], ah[mf], bh[nf]);   // hi*hi
                        mma_bf16(acc[mf][nf], ah[mf], bl[nf]);   // hi*lo
                        mma_bf16(acc[mf][nf], al[mf], bh[nf]);   // lo*hi
                    }
            }
        }

        // store next stage
        if (i + 1 < NC) {
            char* st = smem + ((i + 1) & 1) * STAGEB;
            cvt_store16(st + ST_AHI + grow * ROWB + ghalf * 32,
                        st + ST_ALO + grow * ROWB + ghalf * 32, (const float*)aR);
            cvt_store16(st + ST_BHI + grow * ROWB + ghalf * 32,
                        st + ST_BLO + grow * ROWB + ghalf * 32, (const float*)bR);
        }
        __syncthreads();
    }

    // epilogue: c frag mapping: (row=gid, col=tig*2), (row, col+1),
    // (row+8, col), (row+8, col+1)
    const int gid = lane >> 2, tig = lane & 3;
#pragma unroll
    for (int mf = 0; mf < 4; mf++) {
        int r0 = m0 + wm0 + mf * 16 + gid;
#pragma unroll
        for (int nf = 0; nf < 4; nf++) {
            int c0 = n0 + wn0 + nf * 8 + tig * 2;
            float bx = 0.f, by = 0.f;
            if (HAS_BIAS) { bx = bias[c0]; by = bias[c0 + 1]; }
            float2 v0 = make_float2(acc[mf][nf][0] + bx, acc[mf][nf][1] + by);
            float2 v1 = make_float2(acc[mf][nf][2] + bx, acc[mf][nf][3] + by);
            *(float2*)(Cb + (long)r0 * N + c0) = v0;
            *(float2*)(Cb + (long)(r0 + 8) * N + c0) = v1;
        }
    }
}

// ---------------- transpose: dst[C][R] = src[R][C] --------------------------
__global__ void __launch_bounds__(256)
transpose_kernel(const float* __restrict__ src, float* __restrict__ dst,
                 int R, int C, long sSrc, long sDst)
{
    __shared__ float t[32][33];
    src += (long)blockIdx.z * sSrc;
    dst += (long)blockIdx.z * sDst;
    int x = blockIdx.x * 32 + threadIdx.x;
    int y = blockIdx.y * 32 + threadIdx.y;
#pragma unroll
    for (int j = 0; j < 32; j += 8)
        t[threadIdx.y + j][threadIdx.x] = src[(long)(y + j) * C + x];
    __syncthreads();
    x = blockIdx.y * 32 + threadIdx.x;
    y = blockIdx.x * 32 + threadIdx.y;
#pragma unroll
    for (int j = 0; j < 32; j += 8)
        dst[(long)(y + j) * R + x] = t[threadIdx.x][threadIdx.y + j];
}

// ---------------- softmax ---------------------------------------------------
__global__ void __launch_bounds__(256)
softmax_kernel(float* __restrict__ S)
{
    float* row = S + (long)blockIdx.x * SEQ;
    __shared__ float red[256];
    const int tid = threadIdx.x;

    float m = -INFINITY;
    for (int i = tid; i < SEQ; i += 256) m = fmaxf(m, row[i]);
    red[tid] = m;
    __syncthreads();
    for (int s = 128; s > 0; s >>= 1) {
        if (tid < s) red[tid] = fmaxf(red[tid], red[tid + s]);
        __syncthreads();
    }
    m = red[0];
    __syncthreads();

    float sum = 0.f;
    for (int i = tid; i < SEQ; i += 256) {
        float e = __expf(row[i] - m);
        row[i] = e;
        sum += e;
    }
    red[tid] = sum;
    __syncthreads();
    for (int s = 128; s > 0; s >>= 1) {
        if (tid < s) red[tid] += red[tid + s];
        __syncthreads();
    }
    float inv = 1.f / red[0];
    __syncthreads();
    for (int i = tid; i < SEQ; i += 256) row[i] *= inv;
}

// ---------------------------------------------------------------------------
extern "C" void kernel_launch(void* const* d_in, const int* in_sizes, int n_in,
                              void* d_out, int out_size)
{
    const float* a   = (const float*)d_in[0];
    const float* w_q = (const float*)d_in[1];
    const float* b_q = (const float*)d_in[2];
    const float* w_k = (const float*)d_in[3];
    const float* b_k = (const float*)d_in[4];
    const float* w_v = (const float*)d_in[5];
    const float* b_v = (const float*)d_in[6];
    float* out = (float*)d_out;

    float *q, *k, *v, *s, *wt, *vt;
    cudaGetSymbolAddress((void**)&q,  g_q);
    cudaGetSymbolAddress((void**)&k,  g_k);
    cudaGetSymbolAddress((void**)&v,  g_v);
    cudaGetSymbolAddress((void**)&s,  g_s);
    cudaGetSymbolAddress((void**)&wt, g_wt);
    cudaGetSymbolAddress((void**)&vt, g_vt);

    cudaFuncSetAttribute(bf16x3_gemm_nt<true>,
                         cudaFuncAttributeMaxDynamicSharedMemorySize, SMEM_SZ);
    cudaFuncSetAttribute(bf16x3_gemm_nt<false>,
                         cudaFuncAttributeMaxDynamicSharedMemorySize, SMEM_SZ);

    const int M1 = BATCH * SEQ;   // 8192

    // 0) WT[n][k] = W[k][n]
    {
        dim3 grid(DIM / 32, DIM / 32, 1);
        dim3 blk(32, 8, 1);
        transpose_kernel<<<grid, blk>>>(w_q, wt + 0L * DIM * DIM, DIM, DIM, 0, 0);
        transpose_kernel<<<grid, blk>>>(w_k, wt + 1L * DIM * DIM, DIM, DIM, 0, 0);
        transpose_kernel<<<grid, blk>>>(w_v, wt + 2L * DIM * DIM, DIM, DIM, 0, 0);
    }

    // 1) projections
    {
        dim3 grid(DIM / BN, M1 / BM, 1);
        bf16x3_gemm_nt<true><<<grid, GTHREADS, SMEM_SZ>>>(
            a, wt + 0L * DIM * DIM, b_q, q, M1, DIM, DIM, 0, 0, 0);
        bf16x3_gemm_nt<true><<<grid, GTHREADS, SMEM_SZ>>>(
            a, wt + 1L * DIM * DIM, b_k, k, M1, DIM, DIM, 0, 0, 0);
        bf16x3_gemm_nt<true><<<grid, GTHREADS, SMEM_SZ>>>(
            a, wt + 2L * DIM * DIM, b_v, v, M1, DIM, DIM, 0, 0, 0);
    }

    // 2) VT[b][d][t] = v[b][t][d]
    {
        dim3 grid(DIM / 32, SEQ / 32, BATCH);
        dim3 blk(32, 8, 1);
        transpose_kernel<<<grid, blk>>>(v, vt, SEQ, DIM,
                                        (long)SEQ * DIM, (long)DIM * SEQ);
    }

    // 3) scores = q @ k^T
    {
        dim3 grid(SEQ / BN, SEQ / BM, BATCH);
        bf16x3_gemm_nt<false><<<grid, GTHREADS, SMEM_SZ>>>(
            q, k, nullptr, s, SEQ, SEQ, DIM,
            (long)SEQ * DIM, (long)SEQ * DIM, (long)SEQ * SEQ);
    }

    // 4) softmax
    softmax_kernel<<<BATCH * SEQ, 256>>>(s);

    // 5) out = p @ VT^T
    {
        dim3 grid(DIM / BN, SEQ / BM, BATCH);
        bf16x3_gemm_nt<false><<<grid, GTHREADS, SMEM_SZ>>>(
            s, vt, nullptr, out, SEQ, DIM, SEQ,
            (long)SEQ * SEQ, (long)DIM * SEQ, (long)SEQ * DIM);
    }
}

// round 7
// speedup vs baseline: 2.4573x; 1.1530x over previous
#include <cuda_runtime.h>
#include <cuda_bf16.h>
#include <cstdint>
#include <math.h>

// ---------------------------------------------------------------------------
// Self-attention B=4, S=2048, D=1024 — Round 6.
// bf16x3-split GEMMs on mma.sync.m16n8k16, with ALL fp32->bf16 hi/lo splits
// hoisted out of the GEMM hot loop (operands pre-split in gmem) and cp.async
// 3-stage smem pipeline. Hot loop = ldmatrix + HMMA only.
//
//   ah/al  = split(a)                          (elementwise)
//   wt h/l = split(W^T)                        (transpose+split)
//   q,k,v h/l = gemm(a, wt) + b                (epilogue writes hi/lo)
//   vt h/l = transpose(v h/l)                  (bf16 transpose x2)
//   s      = gemm(q, k)  fp32                  (NT)
//   p h/l  = softmax(s)                        (single read, split write)
//   out    = gemm(p, vt) fp32                  (NT)
// ---------------------------------------------------------------------------

#define BATCH 4
#define SEQ   2048
#define DIM   1024

typedef __nv_bfloat16 bf16;

// ---------------- scratch ---------------------------------------------------
__device__ bf16  g_ah[BATCH * SEQ * DIM], g_al[BATCH * SEQ * DIM];
__device__ bf16  g_wth[3 * DIM * DIM],    g_wtl[3 * DIM * DIM];
__device__ bf16  g_qh[BATCH * SEQ * DIM], g_ql[BATCH * SEQ * DIM];
__device__ bf16  g_kh[BATCH * SEQ * DIM], g_kl[BATCH * SEQ * DIM];
__device__ bf16  g_vh[BATCH * SEQ * DIM], g_vl[BATCH * SEQ * DIM];
__device__ bf16  g_vth[BATCH * DIM * SEQ], g_vtl[BATCH * DIM * SEQ];
__device__ float g_s [BATCH * SEQ * SEQ];
__device__ bf16  g_ph[BATCH * SEQ * SEQ], g_pl[BATCH * SEQ * SEQ];

// ---------------- helpers ---------------------------------------------------
__device__ __forceinline__ uint32_t smem_u32(const void* p) {
    uint32_t a;
    asm("{ .reg .u64 t; cvta.to.shared.u64 t, %1; cvt.u32.u64 %0, t; }"
        : "=r"(a) : "l"(p));
    return a;
}
__device__ __forceinline__ void cp16(uint32_t dst, const void* src) {
    asm volatile("cp.async.cg.shared.global [%0], [%1], 16;"
                 :: "r"(dst), "l"(src));
}
#define CP_COMMIT() asm volatile("cp.async.commit_group;" ::: "memory")
#define CP_WAIT1()  asm volatile("cp.async.wait_group 1;" ::: "memory")

__device__ __forceinline__ void ldm_x4(uint32_t* r, uint32_t addr) {
    asm volatile("ldmatrix.sync.aligned.m8n8.x4.shared.b16 {%0,%1,%2,%3}, [%4];"
                 : "=r"(r[0]), "=r"(r[1]), "=r"(r[2]), "=r"(r[3]) : "r"(addr));
}
__device__ __forceinline__ void mma_bf16(float* c, const uint32_t* a,
                                         const uint32_t* b) {
    asm volatile(
        "mma.sync.aligned.m16n8k16.row.col.f32.bf16.bf16.f32 "
        "{%0,%1,%2,%3}, {%4,%5,%6,%7}, {%8,%9}, {%0,%1,%2,%3};"
        : "+f"(c[0]), "+f"(c[1]), "+f"(c[2]), "+f"(c[3])
        : "r"(a[0]), "r"(a[1]), "r"(a[2]), "r"(a[3]), "r"(b[0]), "r"(b[1]));
}
__device__ __forceinline__ uint32_t bpack(bf16 a, bf16 b) {
    union { __nv_bfloat162 v; uint32_t u; } t;
    t.v = __halves2bfloat162(a, b);
    return t.u;
}
// split two fp32 into packed hi / lo bf16x2 words
__device__ __forceinline__ void split2(float x, float y, uint32_t& hi,
                                       uint32_t& lo) {
    bf16 hx = __float2bfloat16(x), hy = __float2bfloat16(y);
    hi = bpack(hx, hy);
    lo = bpack(__float2bfloat16(x - __bfloat162float(hx)),
               __float2bfloat16(y - __bfloat162float(hy)));
}

// ---------------- GEMM config ----------------------------------------------
#define BM 128
#define BN 128
#define BKE 32                 // bf16 elements per stage (2 x k16)
#define NSTG 3
#define GTHREADS 256           // 8 warps: 2(M) x 4(N), warp tile 64x32

#define ROWB   80              // 64B data + 16B pad per row
#define TILEB  (128 * ROWB)
#define ST_AHI 0
#define ST_ALO (TILEB)
#define ST_BHI (2 * TILEB)
#define ST_BLO (3 * TILEB)
#define STAGEB (4 * TILEB)                  // 40960
#define SMEM_SZ (NSTG * STAGEB)             // 122880

__device__ __forceinline__ void issue_tile(const bf16* src, uint32_t dst,
                                           int K, long k0, int tid) {
#pragma unroll
    for (int rep = 0; rep < 2; rep++) {
        int c = tid + rep * GTHREADS;          // 0..511
        int row = c >> 2, col = c & 3;
        cp16(dst + row * ROWB + col * 16, src + (long)row * K + k0 + col * 8);
    }
}

// NT GEMM: C[m][n] = sum_k A[m][k]*B[n][k]; A,B given as hi/lo bf16 pairs.
template<bool HAS_BIAS, bool SPLIT_OUT>
__global__ void __launch_bounds__(GTHREADS, 1)
bf16x3_gemm(const bf16* __restrict__ Ah, const bf16* __restrict__ Al,
            const bf16* __restrict__ Bh, const bf16* __restrict__ Bl,
            const float* __restrict__ bias,
            float* __restrict__ Cf, bf16* __restrict__ Ch,
            bf16* __restrict__ Cl,
            int M, int N, int K, long sA, long sB, long sC)
{
    extern __shared__ char smem[];
    const uint32_t sbase = smem_u32(smem);
    const int tid  = threadIdx.x;
    const int lane = tid & 31;
    const int wid  = tid >> 5;
    const int wm0  = (wid >> 2) * 64;
    const int wn0  = (wid & 3) * 32;
    const int m0 = blockIdx.y * BM;
    const int n0 = blockIdx.x * BN;

    const bf16* Ahb = Ah + (long)blockIdx.z * sA + (long)m0 * K;
    const bf16* Alb = Al + (long)blockIdx.z * sA + (long)m0 * K;
    const bf16* Bhb = Bh + (long)blockIdx.z * sB + (long)n0 * K;
    const bf16* Blb = Bl + (long)blockIdx.z * sB + (long)n0 * K;

    const uint32_t partA = (uint32_t)((wm0 + (lane & 15)) * ROWB
                                      + ((lane >> 4) << 4));
    const uint32_t partB = (uint32_t)((wn0 + (lane & 7) + ((lane >> 4) << 3)) * ROWB
                                      + ((lane & 8) ? 16 : 0));

    float acc[4][4][4];
#pragma unroll
    for (int i = 0; i < 4; i++)
#pragma unroll
        for (int j = 0; j < 4; j++)
#pragma unroll
            for (int r = 0; r < 4; r++) acc[i][j][r] = 0.f;

    const int NC = K / BKE;

    // prologue: issue stages 0..NSTG-2
#pragma unroll
    for (int s = 0; s < NSTG - 1; s++) {
        uint32_t sb = sbase + s * STAGEB;
        long k0 = (long)s * BKE;
        issue_tile(Ahb, sb + ST_AHI, K, k0, tid);
        issue_tile(Alb, sb + ST_ALO, K, k0, tid);
        issue_tile(Bhb, sb + ST_BHI, K, k0, tid);
        issue_tile(Blb, sb + ST_BLO, K, k0, tid);
        CP_COMMIT();
    }

    for (int i = 0; i < NC; i++) {
        CP_WAIT1();          // stage i resident
        __syncthreads();

        const uint32_t st = sbase + (uint32_t)((i % NSTG) * STAGEB);
#pragma unroll
        for (int ks = 0; ks < 2; ks++) {
            uint32_t ah[4][4], al[4][4], bh[4][2], bl[4][2];
#pragma unroll
            for (int mf = 0; mf < 4; mf++) {
                uint32_t off = (uint32_t)(mf * 16 * ROWB + ks * 32) + partA;
                ldm_x4(ah[mf], st + ST_AHI + off);
                ldm_x4(al[mf], st + ST_ALO + off);
            }
#pragma unroll
            for (int nf2 = 0; nf2 < 2; nf2++) {
                uint32_t off = (uint32_t)(nf2 * 16 * ROWB + ks * 32) + partB;
                uint32_t t[4];
                ldm_x4(t, st + ST_BHI + off);
                bh[nf2 * 2][0] = t[0]; bh[nf2 * 2][1] = t[1];
                bh[nf2 * 2 + 1][0] = t[2]; bh[nf2 * 2 + 1][1] = t[3];
                ldm_x4(t, st + ST_BLO + off);
                bl[nf2 * 2][0] = t[0]; bl[nf2 * 2][1] = t[1];
                bl[nf2 * 2 + 1][0] = t[2]; bl[nf2 * 2 + 1][1] = t[3];
            }
#pragma unroll
            for (int nf = 0; nf < 4; nf++)
#pragma unroll
                for (int mf = 0; mf < 4; mf++) {
                    mma_bf16(acc[mf][nf], ah[mf], bh[nf]);
                    mma_bf16(acc[mf][nf], ah[mf], bl[nf]);
                    mma_bf16(acc[mf][nf], al[mf], bh[nf]);
                }
        }

        // issue stage i+NSTG-1 into slot (i-1)%NSTG (safe: sync above)
        int nxt = i + NSTG - 1;
        if (nxt < NC) {
            uint32_t sb = sbase + (uint32_t)((nxt % NSTG) * STAGEB);
            long k0 = (long)nxt * BKE;
            issue_tile(Ahb, sb + ST_AHI, K, k0, tid);
            issue_tile(Alb, sb + ST_ALO, K, k0, tid);
            issue_tile(Bhb, sb + ST_BHI, K, k0, tid);
            issue_tile(Blb, sb + ST_BLO, K, k0, tid);
        }
        CP_COMMIT();         // commit every iter (possibly empty group)
    }

    // epilogue
    const int gid = lane >> 2, tig = lane & 3;
#pragma unroll
    for (int mf = 0; mf < 4; mf++) {
        int r0 = m0 + wm0 + mf * 16 + gid;
#pragma unroll
        for (int nf = 0; nf < 4; nf++) {
            int c0 = n0 + wn0 + nf * 8 + tig * 2;
            float bx = 0.f, by = 0.f;
            if (HAS_BIAS) { bx = bias[c0]; by = bias[c0 + 1]; }
            float x0 = acc[mf][nf][0] + bx, y0 = acc[mf][nf][1] + by;
            float x1 = acc[mf][nf][2] + bx, y1 = acc[mf][nf][3] + by;
            if (SPLIT_OUT) {
                long o0 = (long)(r0) * N + c0 + (long)blockIdx.z * sC;
                long o1 = (long)(r0 + 8) * N + c0 + (long)blockIdx.z * sC;
                uint32_t h, l;
                split2(x0, y0, h, l);
                *(uint32_t*)(Ch + o0) = h; *(uint32_t*)(Cl + o0) = l;
                split2(x1, y1, h, l);
                *(uint32_t*)(Ch + o1) = h; *(uint32_t*)(Cl + o1) = l;
            } else {
                float* Cb = Cf + (long)blockIdx.z * sC;
                *(float2*)(Cb + (long)r0 * N + c0) = make_float2(x0, y0);
                *(float2*)(Cb + (long)(r0 + 8) * N + c0) = make_float2(x1, y1);
            }
        }
    }
}

// ---------------- split a: fp32 -> hi/lo bf16 -------------------------------
__global__ void __launch_bounds__(256)
split_kernel(const float* __restrict__ src, bf16* __restrict__ h,
             bf16* __restrict__ l)
{
    long idx = (long)blockIdx.x * 256 + threadIdx.x;   // pair index
    float2 v = ((const float2*)src)[idx];
    uint32_t hw, lw;
    split2(v.x, v.y, hw, lw);
    ((uint32_t*)h)[idx] = hw;
    ((uint32_t*)l)[idx] = lw;
}

// ---------------- weight transpose + split: w[k][n] -> wt h/l [n][k] --------
__global__ void __launch_bounds__(256)
wsplit_kernel(const float* __restrict__ w, bf16* __restrict__ h,
              bf16* __restrict__ l)
{
    __shared__ float t[32][33];
    int x = blockIdx.x * 32 + threadIdx.x;     // n
    int y = blockIdx.y * 32 + threadIdx.y;     // k
#pragma unroll
    for (int j = 0; j < 32; j += 8)
        t[threadIdx.y + j][threadIdx.x] = w[(long)(y + j) * DIM + x];
    __syncthreads();
    x = blockIdx.y * 32 + threadIdx.x;         // k
    y = blockIdx.x * 32 + threadIdx.y;         // n
#pragma unroll
    for (int j = 0; j < 32; j += 8) {
        float v = t[threadIdx.x][threadIdx.y + j];
        bf16 hv = __float2bfloat16(v);
        h[(long)(y + j) * DIM + x] = hv;
        l[(long)(y + j) * DIM + x] =
            __float2bfloat16(v - __bfloat162float(hv));
    }
}

// ---------------- bf16 transpose: dst[C][R] = src[R][C] ---------------------
__global__ void __launch_bounds__(256)
transpose_bf16(const uint16_t* __restrict__ src, uint16_t* __restrict__ dst,
               int R, int C, long sS, long sD)
{
    __shared__ uint16_t t[32][33];
    src += (long)blockIdx.z * sS;
    dst += (long)blockIdx.z * sD;
    int x = blockIdx.x * 32 + threadIdx.x;
    int y = blockIdx.y * 32 + threadIdx.y;
#pragma unroll
    for (int j = 0; j < 32; j += 8)
        t[threadIdx.y + j][threadIdx.x] = src[(long)(y + j) * C + x];
    __syncthreads();
    x = blockIdx.y * 32 + threadIdx.x;
    y = blockIdx.x * 32 + threadIdx.y;
#pragma unroll
    for (int j = 0; j < 32; j += 8)
        dst[(long)(y + j) * R + x] = t[threadIdx.x][threadIdx.y + j];
}

// ---------------- softmax: fp32 row -> hi/lo bf16 p -------------------------
__global__ void __launch_bounds__(256)
softmax_split(const float* __restrict__ S, bf16* __restrict__ Ph,
              bf16* __restrict__ Pl)
{
    const float2* row = (const float2*)(S + (long)blockIdx.x * SEQ);
    uint32_t* oh = (uint32_t*)(Ph + (long)blockIdx.x * SEQ);
    uint32_t* ol = (uint32_t*)(Pl + (long)blockIdx.x * SEQ);
    __shared__ float red[256];
    const int tid = threadIdx.x;

    float2 e[4];
#pragma unroll
    for (int j = 0; j < 4; j++) e[j] = row[tid + j * 256];

    float m = -INFINITY;
#pragma unroll
    for (int j = 0; j < 4; j++) m = fmaxf(m, fmaxf(e[j].x, e[j].y));
    red[tid] = m;
    __syncthreads();
    for (int s = 128; s > 0; s >>= 1) {
        if (tid < s) red[tid] = fmaxf(red[tid], red[tid + s]);
        __syncthreads();
    }
    m = red[0];
    __syncthreads();

    float sum = 0.f;
#pragma unroll
    for (int j = 0; j < 4; j++) {
        e[j].x = __expf(e[j].x - m);
        e[j].y = __expf(e[j].y - m);
        sum += e[j].x + e[j].y;
    }
    red[tid] = sum;
    __syncthreads();
    for (int s = 128; s > 0; s >>= 1) {
        if (tid < s) red[tid] += red[tid + s];
        __syncthreads();
    }
    float inv = 1.f / red[0];

#pragma unroll
    for (int j = 0; j < 4; j++) {
        uint32_t h, l;
        split2(e[j].x * inv, e[j].y * inv, h, l);
        oh[tid + j * 256] = h;
        ol[tid + j * 256] = l;
    }
}

// ---------------------------------------------------------------------------
extern "C" void kernel_launch(void* const* d_in, const int* in_sizes, int n_in,
                              void* d_out, int out_size)
{
    const float* a   = (const float*)d_in[0];
    const float* w_q = (const float*)d_in[1];
    const float* b_q = (const float*)d_in[2];
    const float* w_k = (const float*)d_in[3];
    const float* b_k = (const float*)d_in[4];
    const float* w_v = (const float*)d_in[5];
    const float* b_v = (const float*)d_in[6];
    float* out = (float*)d_out;

    bf16 *ah, *al, *wth, *wtl, *qh, *ql, *kh, *kl, *vh, *vl, *vth, *vtl, *ph, *pl;
    float* s;
    cudaGetSymbolAddress((void**)&ah,  g_ah);  cudaGetSymbolAddress((void**)&al,  g_al);
    cudaGetSymbolAddress((void**)&wth, g_wth); cudaGetSymbolAddress((void**)&wtl, g_wtl);
    cudaGetSymbolAddress((void**)&qh,  g_qh);  cudaGetSymbolAddress((void**)&ql,  g_ql);
    cudaGetSymbolAddress((void**)&kh,  g_kh);  cudaGetSymbolAddress((void**)&kl,  g_kl);
    cudaGetSymbolAddress((void**)&vh,  g_vh);  cudaGetSymbolAddress((void**)&vl,  g_vl);
    cudaGetSymbolAddress((void**)&vth, g_vth); cudaGetSymbolAddress((void**)&vtl, g_vtl);
    cudaGetSymbolAddress((void**)&ph,  g_ph);  cudaGetSymbolAddress((void**)&pl,  g_pl);
    cudaGetSymbolAddress((void**)&s,   g_s);

    cudaFuncSetAttribute(bf16x3_gemm<true, true>,
                         cudaFuncAttributeMaxDynamicSharedMemorySize, SMEM_SZ);
    cudaFuncSetAttribute(bf16x3_gemm<false, false>,
                         cudaFuncAttributeMaxDynamicSharedMemorySize, SMEM_SZ);

    const int M1 = BATCH * SEQ;   // 8192

    // 0) operand prep
    split_kernel<<<(long)M1 * DIM / 512, 256>>>(a, ah, al);
    {
        dim3 grid(DIM / 32, DIM / 32, 1);
        dim3 blk(32, 8, 1);
        wsplit_kernel<<<grid, blk>>>(w_q, wth + 0L * DIM * DIM, wtl + 0L * DIM * DIM);
        wsplit_kernel<<<grid, blk>>>(w_k, wth + 1L * DIM * DIM, wtl + 1L * DIM * DIM);
        wsplit_kernel<<<grid, blk>>>(w_v, wth + 2L * DIM * DIM, wtl + 2L * DIM * DIM);
    }

    // 1) projections -> hi/lo outputs
    {
        dim3 grid(DIM / BN, M1 / BM, 1);
        bf16x3_gemm<true, true><<<grid, GTHREADS, SMEM_SZ>>>(
            ah, al, wth + 0L * DIM * DIM, wtl + 0L * DIM * DIM, b_q,
            nullptr, qh, ql, M1, DIM, DIM, 0, 0, 0);
        bf16x3_gemm<true, true><<<grid, GTHREADS, SMEM_SZ>>>(
            ah, al, wth + 1L * DIM * DIM, wtl + 1L * DIM * DIM, b_k,
            nullptr, kh, kl, M1, DIM, DIM, 0, 0, 0);
        bf16x3_gemm<true, true><<<grid, GTHREADS, SMEM_SZ>>>(
            ah, al, wth + 2L * DIM * DIM, wtl + 2L * DIM * DIM, b_v,
            nullptr, vh, vl, M1, DIM, DIM, 0, 0, 0);
    }

    // 2) vt h/l = transpose(v h/l) per batch
    {
        dim3 grid(DIM / 32, SEQ / 32, BATCH);
        dim3 blk(32, 8, 1);
        transpose_bf16<<<grid, blk>>>((const uint16_t*)vh, (uint16_t*)vth,
                                      SEQ, DIM, (long)SEQ * DIM, (long)DIM * SEQ);
        transpose_bf16<<<grid, blk>>>((const uint16_t*)vl, (uint16_t*)vtl,
                                      SEQ, DIM, (long)SEQ * DIM, (long)DIM * SEQ);
    }

    // 3) scores = q @ k^T (fp32 out)
    {
        dim3 grid(SEQ / BN, SEQ / BM, BATCH);
        bf16x3_gemm<false, false><<<grid, GTHREADS, SMEM_SZ>>>(
            qh, ql, kh, kl, nullptr, s, nullptr, nullptr,
            SEQ, SEQ, DIM, (long)SEQ * DIM, (long)SEQ * DIM, (long)SEQ * SEQ);
    }

    // 4) softmax -> p hi/lo
    softmax_split<<<BATCH * SEQ, 256>>>(s, ph, pl);

    // 5) out = p @ vt^T (fp32 out)
    {
        dim3 grid(DIM / BN, SEQ / BM, BATCH);
        bf16x3_gemm<false, false><<<grid, GTHREADS, SMEM_SZ>>>(
            ph, pl, vth, vtl, nullptr, out, nullptr, nullptr,
            SEQ, DIM, SEQ, (long)SEQ * SEQ, (long)DIM * SEQ, (long)SEQ * DIM);
    }
}

// round 8
// speedup vs baseline: 2.8522x; 1.1607x over previous
#include <cuda_runtime.h>
#include <cuda_bf16.h>
#include <cstdint>
#include <math.h>

// ---------------------------------------------------------------------------
// Self-attention B=4, S=2048, D=1024 — Round 7.
// bf16x3-split GEMMs (mma.sync.m16n8k16), operands pre-split in gmem.
// GEMM restructured for 2 CTAs/SM: 128-thread CTAs, 128x64 block tile,
// BKE=64 (4 k16-steps per stage), 2-stage cp.async pipeline, 108KB smem/CTA.
// ---------------------------------------------------------------------------

#define BATCH 4
#define SEQ   2048
#define DIM   1024

typedef __nv_bfloat16 bf16;

// ---------------- scratch ---------------------------------------------------
__device__ bf16  g_ah[BATCH * SEQ * DIM], g_al[BATCH * SEQ * DIM];
__device__ bf16  g_wth[3 * DIM * DIM],    g_wtl[3 * DIM * DIM];
__device__ bf16  g_qh[BATCH * SEQ * DIM], g_ql[BATCH * SEQ * DIM];
__device__ bf16  g_kh[BATCH * SEQ * DIM], g_kl[BATCH * SEQ * DIM];
__device__ bf16  g_vh[BATCH * SEQ * DIM], g_vl[BATCH * SEQ * DIM];
__device__ bf16  g_vth[BATCH * DIM * SEQ], g_vtl[BATCH * DIM * SEQ];
__device__ float g_s [BATCH * SEQ * SEQ];
__device__ bf16  g_ph[BATCH * SEQ * SEQ], g_pl[BATCH * SEQ * SEQ];

// ---------------- helpers ---------------------------------------------------
__device__ __forceinline__ uint32_t smem_u32(const void* p) {
    uint32_t a;
    asm("{ .reg .u64 t; cvta.to.shared.u64 t, %1; cvt.u32.u64 %0, t; }"
        : "=r"(a) : "l"(p));
    return a;
}
__device__ __forceinline__ void cp16(uint32_t dst, const void* src) {
    asm volatile("cp.async.cg.shared.global [%0], [%1], 16;"
                 :: "r"(dst), "l"(src));
}
#define CP_COMMIT() asm volatile("cp.async.commit_group;" ::: "memory")
#define CP_WAIT(n)  asm volatile("cp.async.wait_group %0;" :: "n"(n) : "memory")

__device__ __forceinline__ void ldm_x4(uint32_t* r, uint32_t addr) {
    asm volatile("ldmatrix.sync.aligned.m8n8.x4.shared.b16 {%0,%1,%2,%3}, [%4];"
                 : "=r"(r[0]), "=r"(r[1]), "=r"(r[2]), "=r"(r[3]) : "r"(addr));
}
__device__ __forceinline__ void mma_bf16(float* c, const uint32_t* a,
                                         const uint32_t* b) {
    asm volatile(
        "mma.sync.aligned.m16n8k16.row.col.f32.bf16.bf16.f32 "
        "{%0,%1,%2,%3}, {%4,%5,%6,%7}, {%8,%9}, {%0,%1,%2,%3};"
        : "+f"(c[0]), "+f"(c[1]), "+f"(c[2]), "+f"(c[3])
        : "r"(a[0]), "r"(a[1]), "r"(a[2]), "r"(a[3]), "r"(b[0]), "r"(b[1]));
}
__device__ __forceinline__ uint32_t bpack(bf16 a, bf16 b) {
    union { __nv_bfloat162 v; uint32_t u; } t;
    t.v = __halves2bfloat162(a, b);
    return t.u;
}
__device__ __forceinline__ void split2(float x, float y, uint32_t& hi,
                                       uint32_t& lo) {
    bf16 hx = __float2bfloat16(x), hy = __float2bfloat16(y);
    hi = bpack(hx, hy);
    lo = bpack(__float2bfloat16(x - __bfloat162float(hx)),
               __float2bfloat16(y - __bfloat162float(hy)));
}

// ---------------- GEMM config ----------------------------------------------
#define BM 128
#define BN 64
#define BKE 64                 // bf16 elems per stage (4 x k16)
#define GTHREADS 128           // 4 warps: 2(M) x 2(N), warp tile 64x32

#define ROWB   144             // 128B data + 16B pad
#define AT_B   (128 * ROWB)    // A tile bytes (one of hi/lo)
#define BT_B   (64 * ROWB)
#define ST_AHI 0
#define ST_ALO (AT_B)
#define ST_BHI (2 * AT_B)
#define ST_BLO (2 * AT_B + BT_B)
#define STAGEB (2 * AT_B + 2 * BT_B)        // 55296
#define SMEM_SZ (2 * STAGEB)                // 110592 -> 2 CTAs/SM

// issue one tile (R rows x 64 bf16) into smem stage slot
template<int R>
__device__ __forceinline__ void issue_tile(const bf16* src, uint32_t dst,
                                           int K, long k0, int tid) {
#pragma unroll
    for (int it = 0; it < R * 8 / GTHREADS; it++) {
        int c = tid + it * GTHREADS;
        int row = c >> 3, col = c & 7;
        cp16(dst + row * ROWB + col * 16, src + (long)row * K + k0 + col * 8);
    }
}

// NT GEMM: C[m][n] = sum_k A[m][k]*B[n][k]; A,B as hi/lo bf16 pairs.
template<bool HAS_BIAS, bool SPLIT_OUT>
__global__ void __launch_bounds__(GTHREADS)
bf16x3_gemm(const bf16* __restrict__ Ah, const bf16* __restrict__ Al,
            const bf16* __restrict__ Bh, const bf16* __restrict__ Bl,
            const float* __restrict__ bias,
            float* __restrict__ Cf, bf16* __restrict__ Ch,
            bf16* __restrict__ Cl,
            int M, int N, int K, long sA, long sB, long sC)
{
    extern __shared__ char smem[];
    const uint32_t sbase = smem_u32(smem);
    const int tid  = threadIdx.x;
    const int lane = tid & 31;
    const int wid  = tid >> 5;
    const int wm0  = (wid >> 1) * 64;     // 0 / 64
    const int wn0  = (wid & 1) * 32;      // 0 / 32
    const int m0 = blockIdx.y * BM;
    const int n0 = blockIdx.x * BN;

    const bf16* Ahb = Ah + (long)blockIdx.z * sA + (long)m0 * K;
    const bf16* Alb = Al + (long)blockIdx.z * sA + (long)m0 * K;
    const bf16* Bhb = Bh + (long)blockIdx.z * sB + (long)n0 * K;
    const bf16* Blb = Bl + (long)blockIdx.z * sB + (long)n0 * K;

    const uint32_t partA = (uint32_t)((wm0 + (lane & 15)) * ROWB
                                      + ((lane >> 4) << 4));
    const uint32_t partB = (uint32_t)((wn0 + (lane & 7) + ((lane >> 4) << 3)) * ROWB
                                      + ((lane & 8) ? 16 : 0));

    float acc[4][4][4];
#pragma unroll
    for (int i = 0; i < 4; i++)
#pragma unroll
        for (int j = 0; j < 4; j++)
#pragma unroll
            for (int r = 0; r < 4; r++) acc[i][j][r] = 0.f;

    const int NC = K / BKE;

    // prologue: stage 0
    issue_tile<128>(Ahb, sbase + ST_AHI, K, 0, tid);
    issue_tile<128>(Alb, sbase + ST_ALO, K, 0, tid);
    issue_tile<64> (Bhb, sbase + ST_BHI, K, 0, tid);
    issue_tile<64> (Blb, sbase + ST_BLO, K, 0, tid);
    CP_COMMIT();

    for (int i = 0; i < NC; i++) {
        __syncthreads();   // readers of slot (i+1)&1 (stage i-1) are done
        if (i + 1 < NC) {
            uint32_t sb = sbase + (uint32_t)(((i + 1) & 1) * STAGEB);
            long k0 = (long)(i + 1) * BKE;
            issue_tile<128>(Ahb, sb + ST_AHI, K, k0, tid);
            issue_tile<128>(Alb, sb + ST_ALO, K, k0, tid);
            issue_tile<64> (Bhb, sb + ST_BHI, K, k0, tid);
            issue_tile<64> (Blb, sb + ST_BLO, K, k0, tid);
            CP_COMMIT();
            CP_WAIT(1);    // stage i resident
        } else {
            CP_WAIT(0);
        }
        __syncthreads();

        const uint32_t st = sbase + (uint32_t)((i & 1) * STAGEB);
#pragma unroll
        for (int ks = 0; ks < 4; ks++) {
            uint32_t ah[4][4], al[4][4], bh[4][2], bl[4][2];
#pragma unroll
            for (int mf = 0; mf < 4; mf++) {
                uint32_t off = (uint32_t)(mf * 16 * ROWB + ks * 32) + partA;
                ldm_x4(ah[mf], st + ST_AHI + off);
                ldm_x4(al[mf], st + ST_ALO + off);
            }
#pragma unroll
            for (int nf2 = 0; nf2 < 2; nf2++) {
                uint32_t off = (uint32_t)(nf2 * 16 * ROWB + ks * 32) + partB;
                uint32_t t[4];
                ldm_x4(t, st + ST_BHI + off);
                bh[nf2 * 2][0] = t[0]; bh[nf2 * 2][1] = t[1];
                bh[nf2 * 2 + 1][0] = t[2]; bh[nf2 * 2 + 1][1] = t[3];
                ldm_x4(t, st + ST_BLO + off);
                bl[nf2 * 2][0] = t[0]; bl[nf2 * 2][1] = t[1];
                bl[nf2 * 2 + 1][0] = t[2]; bl[nf2 * 2 + 1][1] = t[3];
            }
#pragma unroll
            for (int nf = 0; nf < 4; nf++)
#pragma unroll
                for (int mf = 0; mf < 4; mf++) {
                    mma_bf16(acc[mf][nf], ah[mf], bh[nf]);
                    mma_bf16(acc[mf][nf], ah[mf], bl[nf]);
                    mma_bf16(acc[mf][nf], al[mf], bh[nf]);
                }
        }
    }

    // epilogue
    const int gid = lane >> 2, tig = lane & 3;
#pragma unroll
    for (int mf = 0; mf < 4; mf++) {
        int r0 = m0 + wm0 + mf * 16 + gid;
#pragma unroll
        for (int nf = 0; nf < 4; nf++) {
            int c0 = n0 + wn0 + nf * 8 + tig * 2;
            float bx = 0.f, by = 0.f;
            if (HAS_BIAS) { bx = bias[c0]; by = bias[c0 + 1]; }
            float x0 = acc[mf][nf][0] + bx, y0 = acc[mf][nf][1] + by;
            float x1 = acc[mf][nf][2] + bx, y1 = acc[mf][nf][3] + by;
            if (SPLIT_OUT) {
                long o0 = (long)(r0) * N + c0 + (long)blockIdx.z * sC;
                long o1 = (long)(r0 + 8) * N + c0 + (long)blockIdx.z * sC;
                uint32_t h, l;
                split2(x0, y0, h, l);
                *(uint32_t*)(Ch + o0) = h; *(uint32_t*)(Cl + o0) = l;
                split2(x1, y1, h, l);
                *(uint32_t*)(Ch + o1) = h; *(uint32_t*)(Cl + o1) = l;
            } else {
                float* Cb = Cf + (long)blockIdx.z * sC;
                *(float2*)(Cb + (long)r0 * N + c0) = make_float2(x0, y0);
                *(float2*)(Cb + (long)(r0 + 8) * N + c0) = make_float2(x1, y1);
            }
        }
    }
}

// ---------------- split a ---------------------------------------------------
__global__ void __launch_bounds__(256)
split_kernel(const float* __restrict__ src, bf16* __restrict__ h,
             bf16* __restrict__ l)
{
    long idx = (long)blockIdx.x * 256 + threadIdx.x;
    float2 v = ((const float2*)src)[idx];
    uint32_t hw, lw;
    split2(v.x, v.y, hw, lw);
    ((uint32_t*)h)[idx] = hw;
    ((uint32_t*)l)[idx] = lw;
}

// ---------------- weight transpose + split ----------------------------------
__global__ void __launch_bounds__(256)
wsplit_kernel(const float* __restrict__ w, bf16* __restrict__ h,
              bf16* __restrict__ l)
{
    __shared__ float t[32][33];
    int x = blockIdx.x * 32 + threadIdx.x;
    int y = blockIdx.y * 32 + threadIdx.y;
#pragma unroll
    for (int j = 0; j < 32; j += 8)
        t[threadIdx.y + j][threadIdx.x] = w[(long)(y + j) * DIM + x];
    __syncthreads();
    x = blockIdx.y * 32 + threadIdx.x;
    y = blockIdx.x * 32 + threadIdx.y;
#pragma unroll
    for (int j = 0; j < 32; j += 8) {
        float v = t[threadIdx.x][threadIdx.y + j];
        bf16 hv = __float2bfloat16(v);
        h[(long)(y + j) * DIM + x] = hv;
        l[(long)(y + j) * DIM + x] =
            __float2bfloat16(v - __bfloat162float(hv));
    }
}

// ---------------- bf16 transpose --------------------------------------------
__global__ void __launch_bounds__(256)
transpose_bf16(const uint16_t* __restrict__ src, uint16_t* __restrict__ dst,
               int R, int C, long sS, long sD)
{
    __shared__ uint16_t t[32][33];
    src += (long)blockIdx.z * sS;
    dst += (long)blockIdx.z * sD;
    int x = blockIdx.x * 32 + threadIdx.x;
    int y = blockIdx.y * 32 + threadIdx.y;
#pragma unroll
    for (int j = 0; j < 32; j += 8)
        t[threadIdx.y + j][threadIdx.x] = src[(long)(y + j) * C + x];
    __syncthreads();
    x = blockIdx.y * 32 + threadIdx.x;
    y = blockIdx.x * 32 + threadIdx.y;
#pragma unroll
    for (int j = 0; j < 32; j += 8)
        dst[(long)(y + j) * R + x] = t[threadIdx.x][threadIdx.y + j];
}

// ---------------- softmax -> hi/lo ------------------------------------------
__global__ void __launch_bounds__(256)
softmax_split(const float* __restrict__ S, bf16* __restrict__ Ph,
              bf16* __restrict__ Pl)
{
    const float2* row = (const float2*)(S + (long)blockIdx.x * SEQ);
    uint32_t* oh = (uint32_t*)(Ph + (long)blockIdx.x * SEQ);
    uint32_t* ol = (uint32_t*)(Pl + (long)blockIdx.x * SEQ);
    __shared__ float red[256];
    const int tid = threadIdx.x;

    float2 e[4];
#pragma unroll
    for (int j = 0; j < 4; j++) e[j] = row[tid + j * 256];

    float m = -INFINITY;
#pragma unroll
    for (int j = 0; j < 4; j++) m = fmaxf(m, fmaxf(e[j].x, e[j].y));
    red[tid] = m;
    __syncthreads();
    for (int s = 128; s > 0; s >>= 1) {
        if (tid < s) red[tid] = fmaxf(red[tid], red[tid + s]);
        __syncthreads();
    }
    m = red[0];
    __syncthreads();

    float sum = 0.f;
#pragma unroll
    for (int j = 0; j < 4; j++) {
        e[j].x = __expf(e[j].x - m);
        e[j].y = __expf(e[j].y - m);
        sum += e[j].x + e[j].y;
    }
    red[tid] = sum;
    __syncthreads();
    for (int s = 128; s > 0; s >>= 1) {
        if (tid < s) red[tid] += red[tid + s];
        __syncthreads();
    }
    float inv = 1.f / red[0];

#pragma unroll
    for (int j = 0; j < 4; j++) {
        uint32_t h, l;
        split2(e[j].x * inv, e[j].y * inv, h, l);
        oh[tid + j * 256] = h;
        ol[tid + j * 256] = l;
    }
}

// ---------------------------------------------------------------------------
extern "C" void kernel_launch(void* const* d_in, const int* in_sizes, int n_in,
                              void* d_out, int out_size)
{
    const float* a   = (const float*)d_in[0];
    const float* w_q = (const float*)d_in[1];
    const float* b_q = (const float*)d_in[2];
    const float* w_k = (const float*)d_in[3];
    const float* b_k = (const float*)d_in[4];
    const float* w_v = (const float*)d_in[5];
    const float* b_v = (const float*)d_in[6];
    float* out = (float*)d_out;

    bf16 *ah, *al, *wth, *wtl, *qh, *ql, *kh, *kl, *vh, *vl, *vth, *vtl, *ph, *pl;
    float* s;
    cudaGetSymbolAddress((void**)&ah,  g_ah);  cudaGetSymbolAddress((void**)&al,  g_al);
    cudaGetSymbolAddress((void**)&wth, g_wth); cudaGetSymbolAddress((void**)&wtl, g_wtl);
    cudaGetSymbolAddress((void**)&qh,  g_qh);  cudaGetSymbolAddress((void**)&ql,  g_ql);
    cudaGetSymbolAddress((void**)&kh,  g_kh);  cudaGetSymbolAddress((void**)&kl,  g_kl);
    cudaGetSymbolAddress((void**)&vh,  g_vh);  cudaGetSymbolAddress((void**)&vl,  g_vl);
    cudaGetSymbolAddress((void**)&vth, g_vth); cudaGetSymbolAddress((void**)&vtl, g_vtl);
    cudaGetSymbolAddress((void**)&ph,  g_ph);  cudaGetSymbolAddress((void**)&pl,  g_pl);
    cudaGetSymbolAddress((void**)&s,   g_s);

    cudaFuncSetAttribute(bf16x3_gemm<true, true>,
                         cudaFuncAttributeMaxDynamicSharedMemorySize, SMEM_SZ);
    cudaFuncSetAttribute(bf16x3_gemm<false, false>,
                         cudaFuncAttributeMaxDynamicSharedMemorySize, SMEM_SZ);

    const int M1 = BATCH * SEQ;   // 8192

    // 0) operand prep
    split_kernel<<<(long)M1 * DIM / 512, 256>>>(a, ah, al);
    {
        dim3 grid(DIM / 32, DIM / 32, 1);
        dim3 blk(32, 8, 1);
        wsplit_kernel<<<grid, blk>>>(w_q, wth + 0L * DIM * DIM, wtl + 0L * DIM * DIM);
        wsplit_kernel<<<grid, blk>>>(w_k, wth + 1L * DIM * DIM, wtl + 1L * DIM * DIM);
        wsplit_kernel<<<grid, blk>>>(w_v, wth + 2L * DIM * DIM, wtl + 2L * DIM * DIM);
    }

    // 1) projections -> hi/lo outputs
    {
        dim3 grid(DIM / BN, M1 / BM, 1);
        bf16x3_gemm<true, true><<<grid, GTHREADS, SMEM_SZ>>>(
            ah, al, wth + 0L * DIM * DIM, wtl + 0L * DIM * DIM, b_q,
            nullptr, qh, ql, M1, DIM, DIM, 0, 0, 0);
        bf16x3_gemm<true, true><<<grid, GTHREADS, SMEM_SZ>>>(
            ah, al, wth + 1L * DIM * DIM, wtl + 1L * DIM * DIM, b_k,
            nullptr, kh, kl, M1, DIM, DIM, 0, 0, 0);
        bf16x3_gemm<true, true><<<grid, GTHREADS, SMEM_SZ>>>(
            ah, al, wth + 2L * DIM * DIM, wtl + 2L * DIM * DIM, b_v,
            nullptr, vh, vl, M1, DIM, DIM, 0, 0, 0);
    }

    // 2) vt h/l = transpose(v h/l)
    {
        dim3 grid(DIM / 32, SEQ / 32, BATCH);
        dim3 blk(32, 8, 1);
        transpose_bf16<<<grid, blk>>>((const uint16_t*)vh, (uint16_t*)vth,
                                      SEQ, DIM, (long)SEQ * DIM, (long)DIM * SEQ);
        transpose_bf16<<<grid, blk>>>((const uint16_t*)vl, (uint16_t*)vtl,
                                      SEQ, DIM, (long)SEQ * DIM, (long)DIM * SEQ);
    }

    // 3) scores = q @ k^T (fp32 out)
    {
        dim3 grid(SEQ / BN, SEQ / BM, BATCH);
        bf16x3_gemm<false, false><<<grid, GTHREADS, SMEM_SZ>>>(
            qh, ql, kh, kl, nullptr, s, nullptr, nullptr,
            SEQ, SEQ, DIM, (long)SEQ * DIM, (long)SEQ * DIM, (long)SEQ * SEQ);
    }

    // 4) softmax -> p hi/lo
    softmax_split<<<BATCH * SEQ, 256>>>(s, ph, pl);

    // 5) out = p @ vt^T (fp32 out)
    {
        dim3 grid(DIM / BN, SEQ / BM, BATCH);
        bf16x3_gemm<false, false><<<grid, GTHREADS, SMEM_SZ>>>(
            ph, pl, vth, vtl, nullptr, out, nullptr, nullptr,
            SEQ, DIM, SEQ, (long)SEQ * SEQ, (long)DIM * SEQ, (long)SEQ * DIM);
    }
}